// round 13
// baseline (speedup 1.0000x reference)
#include <cuda_runtime.h>
#include <cuda_fp16.h>
#include <cstdint>

// SoftMesh MLP via warp-level HMMA with SPLIT-FP16 operands (hi+lo), fp32 acc.
// [N,3] ->50 -> 7x(50 tanh) -> 3, N=2M.
// R12: m=1 tile per warp (16 rows), 16 warps / 512 thr, TILE_M=256.
// Same per-point MMA count as R11; more warps + shorter chains for overlap.
// Per-warp regs ~100 < 128 clamp (R10's failure mode was clamp-starvation).
// C += Ah*Bh + Ah*Bl + Al*Bh; ~22 effective mantissa bits.

#define HID 50
#define NB 7
#define NLAYER 8
#define TILE_M 256
#define THREADS 512
#define GRIDSZ 148

// SMEM layout (uint32 indices) — fragment tables keep the kb-major layout
#define BFH_OFF  0
#define BF_SZ    (NLAYER * 4 * NB * 64)        // 14336 per set
#define BFL_OFF  (BFH_OFF + BF_SZ)
#define OFH_OFF  (BFL_OFF + BF_SZ)             // out-layer hi frags [kb][lane*2+r]
#define OF_SZ    (4 * 64)
#define OFL_OFF  (OFH_OFF + OF_SZ)
#define BIAS_OFF (OFL_OFF + OF_SZ)             // float bias[L][nb][t][2]
#define BIAS_SZ  (NLAYER * NB * 4 * 2)
#define OBIAS_OFF (BIAS_OFF + BIAS_SZ)         // float [4][2]
#define OBIAS_SZ 8
#define XYZ_OFF  (OBIAS_OFF + OBIAS_SZ)        // float [3][TILE_M]
#define XYZ_SZ   (3 * TILE_M)
#define UOUT_OFF (XYZ_OFF + XYZ_SZ)            // float [3][TILE_M]
#define UOUT_SZ  (3 * TILE_M)
#define SMEM_U32 (UOUT_OFF + UOUT_SZ)

__device__ __forceinline__ uint32_t f16x2(float lo, float hi) {
    uint32_t r;
    asm("cvt.rn.f16x2.f32 %0, %1, %2;" : "=r"(r) : "f"(hi), "f"(lo));
    return r;
}
// pack two floats into f16x2 hi + f16x2 lo (residual)
__device__ __forceinline__ void split2(float v0, float v1, uint32_t& hi, uint32_t& lo) {
    hi = f16x2(v0, v1);
    __half2 h2 = *reinterpret_cast<__half2*>(&hi);
    float2 b = __half22float2(h2);
    lo = f16x2(v0 - b.x, v1 - b.y);
}
// tanh on a pair with ONE shared rcp: r=rcp(s0*s1); 1/s0=s1*r; 1/s1=s0*r.
__device__ __forceinline__ void tanh_split2(float x0, float x1, uint32_t& hi, uint32_t& lo) {
    const float K = 2.8853900817779268f;  // 2/ln2
    float e0, e1, r;
    asm("ex2.approx.f32 %0, %1;" : "=f"(e0) : "f"(x0 * K));
    asm("ex2.approx.f32 %0, %1;" : "=f"(e1) : "f"(x1 * K));
    float s0 = e0 + 1.0f, s1 = e1 + 1.0f;
    asm("rcp.approx.f32 %0, %1;" : "=f"(r) : "f"(s0 * s1));
    float t0 = fmaf(-2.0f, s1 * r, 1.0f);
    float t1 = fmaf(-2.0f, s0 * r, 1.0f);
    split2(t0, t1, hi, lo);
}
__device__ __forceinline__ void mma16816(float* c, const uint32_t* a, uint32_t b0, uint32_t b1) {
    asm volatile(
        "mma.sync.aligned.m16n8k16.row.col.f32.f16.f16.f32 "
        "{%0,%1,%2,%3}, {%4,%5,%6,%7}, {%8,%9}, {%0,%1,%2,%3};"
        : "+f"(c[0]), "+f"(c[1]), "+f"(c[2]), "+f"(c[3])
        : "r"(a[0]), "r"(a[1]), "r"(a[2]), "r"(a[3]), "r"(b0), "r"(b1));
}
__device__ __forceinline__ void mma16808(float* c, const uint32_t* a, uint32_t b0) {
    asm volatile(
        "mma.sync.aligned.m16n8k8.row.col.f32.f16.f16.f32 "
        "{%0,%1,%2,%3}, {%4,%5}, {%6}, {%0,%1,%2,%3};"
        : "+f"(c[0]), "+f"(c[1]), "+f"(c[2]), "+f"(c[3])
        : "r"(a[0]), "r"(a[1]), "r"(b0));
}

extern __shared__ uint32_t smu[];

__global__ __launch_bounds__(THREADS, 1)
void softmesh_hmma6_kernel(
    const float* __restrict__ x, const float* __restrict__ y,
    const float* __restrict__ z,
    const float* __restrict__ W_in,  const float* __restrict__ b_in,
    const float* __restrict__ W_mid, const float* __restrict__ b_mid,
    const float* __restrict__ W_out, const float* __restrict__ b_out,
    float* __restrict__ out, int n)
{
    float* smf = (float*)smu;
    const int tid = threadIdx.x;

    // ---- Stage weight fragments hi+lo (once per persistent CTA) ----
    for (int i = tid; i < BF_SZ; i += THREADS) {
        int lane = (i & 63) >> 1, r = i & 1;
        int rest = i >> 6;
        int nb = rest % NB; rest /= NB;
        int kb = rest & 3;  int L = rest >> 2;
        int t = lane & 3, g = lane >> 2;
        int nn = nb * 8 + g;
        int k0 = kb * 16 + t * 2 + (r ? 8 : 0);
        float v0 = 0.f, v1 = 0.f;
        if (nn < HID) {
            if (L == 0) {
                if (k0 < 3)     v0 = W_in[k0 * HID + nn];
                if (k0 + 1 < 3) v1 = W_in[(k0 + 1) * HID + nn];
            } else {
                const float* W = W_mid + (size_t)(L - 1) * HID * HID;
                if (k0 < HID)     v0 = W[k0 * HID + nn];
                if (k0 + 1 < HID) v1 = W[(k0 + 1) * HID + nn];
            }
        }
        uint32_t hi, lo;
        split2(v0, v1, hi, lo);
        smu[BFH_OFF + i] = hi;
        smu[BFL_OFF + i] = lo;
    }
    for (int i = tid; i < OF_SZ; i += THREADS) {
        int lane = (i & 63) >> 1, r = i & 1;
        int kb = i >> 6;
        int t = lane & 3, g = lane >> 2;
        int nn = g;  // nblk 0 only
        int k0 = kb * 16 + t * 2 + (r ? 8 : 0);
        float v0 = 0.f, v1 = 0.f;
        if (nn < 3) {
            if (k0 < HID)     v0 = W_out[k0 * 3 + nn];
            if (k0 + 1 < HID) v1 = W_out[(k0 + 1) * 3 + nn];
        }
        uint32_t hi, lo;
        split2(v0, v1, hi, lo);
        smu[OFH_OFF + i] = hi;
        smu[OFL_OFF + i] = lo;
    }
    for (int i = tid; i < BIAS_SZ; i += THREADS) {
        int c = i & 1, t = (i >> 1) & 3;
        int rest = i >> 3;
        int nb = rest % NB, L = rest / NB;
        int col = nb * 8 + t * 2 + c;
        float v = 0.f;
        if (col < HID) v = (L == 0) ? b_in[col] : b_mid[(L - 1) * HID + col];
        smf[BIAS_OFF + i] = v;
    }
    if (tid < 8) {
        int c = tid & 1, t = tid >> 1;
        int col = t * 2 + c;
        smf[OBIAS_OFF + tid] = (col < 3) ? b_out[col] : 0.f;
    }
    __syncthreads();

    const int lane = tid & 31, w = tid >> 5;
    const int g = lane >> 2, t = lane & 3;
    const int ntiles = (n + TILE_M - 1) / TILE_M;

    for (int tile = blockIdx.x; tile < ntiles; tile += (int)gridDim.x) {
        // each warp owns rows [w*16, w*16+16); each thread stages rows via
        // a half-warp view: thread tid covers tile rows tid/2 ... use simple
        // per-thread staging of row = tid % TILE_M over 2 passes worth of cols.
        // Simpler: thread i stages point (tile*TILE_M + i%TILE_M) component i/TILE_M? 
        // Keep it simple & warp-local: threads 2k stage row pairs below.
        const int p = tile * TILE_M + (tid & (TILE_M - 1));
        {
            // 512 threads stage 3*256 floats: thread tid handles element tid and tid+512 (if <768)
            int e0 = tid;                 // 0..511
            int comp0 = e0 >> 8, row0 = e0 & 255;
            int gp0 = tile * TILE_M + row0;
            const float* src0 = (comp0 == 0) ? x : y;
            smf[XYZ_OFF + e0] = (gp0 < n) ? src0[gp0] : 0.f;
            int e1 = tid + 512;           // 512..1023 -> only 512..767 valid
            if (e1 < 3 * TILE_M) {
                int row1 = e1 & 255;
                int gp1 = tile * TILE_M + row1;
                smf[XYZ_OFF + e1] = (gp1 < n) ? z[gp1] : 0.f;
            }
        }
        __syncthreads();

        uint32_t Ah[4][4], Al[4][4];
        float    c[NB][4];

        // ---- layer 0 A fragments (k<=3 -> only regs [0],[1] used, k8 MMA) ----
        {
            int r0 = w * 16 + g;
            int r1 = r0 + 8;
            uint32_t h0 = 0, h1 = 0, l0 = 0, l1 = 0;
            if (t == 0) {
                split2(smf[XYZ_OFF + r0], smf[XYZ_OFF + TILE_M + r0], h0, l0);
                split2(smf[XYZ_OFF + r1], smf[XYZ_OFF + TILE_M + r1], h1, l1);
            } else if (t == 1) {
                split2(smf[XYZ_OFF + 2 * TILE_M + r0], 0.f, h0, l0);
                split2(smf[XYZ_OFF + 2 * TILE_M + r1], 0.f, h1, l1);
            }
            Ah[0][0] = h0; Ah[0][1] = h1;
            Al[0][0] = l0; Al[0][1] = l1;
        }

        // ---- layer 0 GEMM: k8 MMAs (3 products) ----
        #pragma unroll
        for (int nb = 0; nb < NB; ++nb) {
            float2 bb = *(const float2*)&smf[BIAS_OFF + (nb * 4 + t) * 2];
            c[nb][0] = bb.x; c[nb][1] = bb.y;
            c[nb][2] = bb.x; c[nb][3] = bb.y;
            uint32_t bh = smu[BFH_OFF + nb * 64 + lane * 2];
            uint32_t bl = smu[BFL_OFF + nb * 64 + lane * 2];
            mma16808(c[nb], Ah[0], bh);
            mma16808(c[nb], Ah[0], bl);
            mma16808(c[nb], Al[0], bh);
        }
        #pragma unroll
        for (int kb = 0; kb < 3; ++kb) {
            tanh_split2(c[2*kb][0],   c[2*kb][1],   Ah[kb][0], Al[kb][0]);
            tanh_split2(c[2*kb][2],   c[2*kb][3],   Ah[kb][1], Al[kb][1]);
            tanh_split2(c[2*kb+1][0], c[2*kb+1][1], Ah[kb][2], Al[kb][2]);
            tanh_split2(c[2*kb+1][2], c[2*kb+1][3], Ah[kb][3], Al[kb][3]);
        }
        tanh_split2(c[6][0], c[6][1], Ah[3][0], Al[3][0]);
        tanh_split2(c[6][2], c[6][3], Ah[3][1], Al[3][1]);

        // ---- layers 1..7: kb 0..2 k16 + kb3 k8 ----
        #pragma unroll 1
        for (int L = 1; L < NLAYER; ++L) {
            const uint32_t* bhl = &smu[BFH_OFF + (size_t)L * 4 * NB * 64];
            const uint32_t* bll = &smu[BFL_OFF + (size_t)L * 4 * NB * 64];
            const float*    bil = &smf[BIAS_OFF + (size_t)L * NB * 8];
            #pragma unroll
            for (int nb = 0; nb < NB; ++nb) {
                float2 bb = *(const float2*)&bil[(nb * 4 + t) * 2];
                c[nb][0] = bb.x; c[nb][1] = bb.y;
                c[nb][2] = bb.x; c[nb][3] = bb.y;
            }
            #pragma unroll
            for (int kb = 0; kb < 3; ++kb) {
                #pragma unroll
                for (int nb = 0; nb < NB; ++nb) {
                    uint2 bh = *(const uint2*)&bhl[(kb * NB + nb) * 64 + lane * 2];
                    uint2 bl = *(const uint2*)&bll[(kb * NB + nb) * 64 + lane * 2];
                    mma16816(c[nb], Ah[kb], bh.x, bh.y);
                    mma16816(c[nb], Ah[kb], bl.x, bl.y);
                    mma16816(c[nb], Al[kb], bh.x, bh.y);
                }
            }
            #pragma unroll
            for (int nb = 0; nb < NB; ++nb) {   // kb = 3: k8 (only k=48,49 real)
                uint32_t bh = bhl[(3 * NB + nb) * 64 + lane * 2];
                uint32_t bl = bll[(3 * NB + nb) * 64 + lane * 2];
                mma16808(c[nb], Ah[3], bh);
                mma16808(c[nb], Ah[3], bl);
                mma16808(c[nb], Al[3], bh);
            }
            #pragma unroll
            for (int kb = 0; kb < 3; ++kb) {
                tanh_split2(c[2*kb][0],   c[2*kb][1],   Ah[kb][0], Al[kb][0]);
                tanh_split2(c[2*kb][2],   c[2*kb][3],   Ah[kb][1], Al[kb][1]);
                tanh_split2(c[2*kb+1][0], c[2*kb+1][1], Ah[kb][2], Al[kb][2]);
                tanh_split2(c[2*kb+1][2], c[2*kb+1][3], Ah[kb][3], Al[kb][3]);
            }
            tanh_split2(c[6][0], c[6][1], Ah[3][0], Al[3][0]);
            tanh_split2(c[6][2], c[6][3], Ah[3][1], Al[3][1]);
        }

        // ---- output layer 50->3 (nblk 0 only), no tanh ----
        float o[4];
        {
            float2 bb = *(const float2*)&smf[OBIAS_OFF + t * 2];
            o[0] = bb.x; o[1] = bb.y; o[2] = bb.x; o[3] = bb.y;
            #pragma unroll
            for (int kb = 0; kb < 3; ++kb) {
                uint2 bh = *(const uint2*)&smu[OFH_OFF + kb * 64 + lane * 2];
                uint2 bl = *(const uint2*)&smu[OFL_OFF + kb * 64 + lane * 2];
                mma16816(o, Ah[kb], bh.x, bh.y);
                mma16816(o, Ah[kb], bl.x, bl.y);
                mma16816(o, Al[kb], bh.x, bh.y);
            }
            uint32_t bh = smu[OFH_OFF + 3 * 64 + lane * 2];
            uint32_t bl = smu[OFL_OFF + 3 * 64 + lane * 2];
            mma16808(o, Ah[3], bh);
            mma16808(o, Ah[3], bl);
            mma16808(o, Al[3], bh);
        }
        // scatter U to staging (warp rows): t==0 -> cols 0,1 ; t==1 -> col 2
        {
            int r0 = w * 16 + g;
            int r1 = r0 + 8;
            if (t == 0) {
                smf[UOUT_OFF + r0] = o[0];
                smf[UOUT_OFF + TILE_M + r0] = o[1];
                smf[UOUT_OFF + r1] = o[2];
                smf[UOUT_OFF + TILE_M + r1] = o[3];
            } else if (t == 1) {
                smf[UOUT_OFF + 2 * TILE_M + r0] = o[0];
                smf[UOUT_OFF + 2 * TILE_M + r1] = o[2];
            }
        }
        __syncthreads();
        // 512 threads write 3*256 outputs: thread tid -> element tid, tid+512
        {
            int e0 = tid;
            int comp0 = e0 >> 8, row0 = e0 & 255;
            int gp0 = tile * TILE_M + row0;
            if (gp0 < n) out[(size_t)comp0 * n + gp0] = smf[UOUT_OFF + e0];
            int e1 = tid + 512;
            if (e1 < 3 * TILE_M) {
                int row1 = e1 & 255;
                int gp1 = tile * TILE_M + row1;
                if (gp1 < n) out[2 * (size_t)n + gp1] = smf[UOUT_OFF + e1];
            }
        }
        __syncthreads();
        (void)p;
    }
}

extern "C" void kernel_launch(void* const* d_in, const int* in_sizes, int n_in,
                              void* d_out, int out_size) {
    const float* x     = (const float*)d_in[0];
    const float* y     = (const float*)d_in[1];
    const float* z     = (const float*)d_in[2];
    const float* W_in  = (const float*)d_in[3];
    const float* b_in  = (const float*)d_in[4];
    const float* W_mid = (const float*)d_in[5];
    const float* b_mid = (const float*)d_in[6];
    const float* W_out = (const float*)d_in[7];
    const float* b_out = (const float*)d_in[8];
    float* out = (float*)d_out;
    const int n = in_sizes[0];

    const size_t smem_bytes = (size_t)SMEM_U32 * 4;
    cudaFuncSetAttribute(softmesh_hmma6_kernel,
                         cudaFuncAttributeMaxDynamicSharedMemorySize,
                         (int)smem_bytes);

    softmesh_hmma6_kernel<<<GRIDSZ, THREADS, smem_bytes>>>(
        x, y, z, W_in, b_in, W_mid, b_mid, W_out, b_out, out, n);
}

// round 14
// speedup vs baseline: 1.0005x; 1.0005x over previous
#include <cuda_runtime.h>
#include <cuda_fp16.h>
#include <cstdint>

// SoftMesh MLP via warp-level HMMA with SPLIT-FP16 operands (hi+lo), fp32 acc.
// [N,3] ->50 -> 7x(50 tanh) -> 3, N=2M.
// R14 = R11 (384 thr, 12 warps, m=2 tiles/warp) with the layer body
// software-pipelined across the two INDEPENDENT m-tiles:
//   { tanh m0 -> MMA m0 ; tanh m1 -> MMA m1 }
// so tanh(m1) overlaps MMA(m0)'s tensor drain and vice versa across layers.
// C += Ah*Bh + Ah*Bl + Al*Bh; ~22 effective mantissa bits.

#define HID 50
#define NB 7
#define NLAYER 8
#define TILE_M 384
#define THREADS 384
#define GRIDSZ 148

// SMEM layout (uint32 indices) — fragment tables keep the kb-major layout
#define BFH_OFF  0
#define BF_SZ    (NLAYER * 4 * NB * 64)        // 14336 per set
#define BFL_OFF  (BFH_OFF + BF_SZ)
#define OFH_OFF  (BFL_OFF + BF_SZ)             // out-layer hi frags [kb][lane*2+r]
#define OF_SZ    (4 * 64)
#define OFL_OFF  (OFH_OFF + OF_SZ)
#define BIAS_OFF (OFL_OFF + OF_SZ)             // float bias[L][nb][t][2]
#define BIAS_SZ  (NLAYER * NB * 4 * 2)
#define OBIAS_OFF (BIAS_OFF + BIAS_SZ)         // float [4][2]
#define OBIAS_SZ 8
#define XYZ_OFF  (OBIAS_OFF + OBIAS_SZ)        // float [3][TILE_M]
#define XYZ_SZ   (3 * TILE_M)
#define UOUT_OFF (XYZ_OFF + XYZ_SZ)            // float [3][TILE_M]
#define UOUT_SZ  (3 * TILE_M)
#define SMEM_U32 (UOUT_OFF + UOUT_SZ)

__device__ __forceinline__ uint32_t f16x2(float lo, float hi) {
    uint32_t r;
    asm("cvt.rn.f16x2.f32 %0, %1, %2;" : "=r"(r) : "f"(hi), "f"(lo));
    return r;
}
// pack two floats into f16x2 hi + f16x2 lo (residual)
__device__ __forceinline__ void split2(float v0, float v1, uint32_t& hi, uint32_t& lo) {
    hi = f16x2(v0, v1);
    __half2 h2 = *reinterpret_cast<__half2*>(&hi);
    float2 b = __half22float2(h2);
    lo = f16x2(v0 - b.x, v1 - b.y);
}
// tanh on a pair with ONE shared rcp: r=rcp(s0*s1); 1/s0=s1*r; 1/s1=s0*r.
__device__ __forceinline__ void tanh_split2(float x0, float x1, uint32_t& hi, uint32_t& lo) {
    const float K = 2.8853900817779268f;  // 2/ln2
    float e0, e1, r;
    asm("ex2.approx.f32 %0, %1;" : "=f"(e0) : "f"(x0 * K));
    asm("ex2.approx.f32 %0, %1;" : "=f"(e1) : "f"(x1 * K));
    float s0 = e0 + 1.0f, s1 = e1 + 1.0f;
    asm("rcp.approx.f32 %0, %1;" : "=f"(r) : "f"(s0 * s1));
    float t0 = fmaf(-2.0f, s1 * r, 1.0f);
    float t1 = fmaf(-2.0f, s0 * r, 1.0f);
    split2(t0, t1, hi, lo);
}
__device__ __forceinline__ void mma16816(float* c, const uint32_t* a, uint32_t b0, uint32_t b1) {
    asm volatile(
        "mma.sync.aligned.m16n8k16.row.col.f32.f16.f16.f32 "
        "{%0,%1,%2,%3}, {%4,%5,%6,%7}, {%8,%9}, {%0,%1,%2,%3};"
        : "+f"(c[0]), "+f"(c[1]), "+f"(c[2]), "+f"(c[3])
        : "r"(a[0]), "r"(a[1]), "r"(a[2]), "r"(a[3]), "r"(b0), "r"(b1));
}
__device__ __forceinline__ void mma16808(float* c, const uint32_t* a, uint32_t b0) {
    asm volatile(
        "mma.sync.aligned.m16n8k8.row.col.f32.f16.f16.f32 "
        "{%0,%1,%2,%3}, {%4,%5}, {%6}, {%0,%1,%2,%3};"
        : "+f"(c[0]), "+f"(c[1]), "+f"(c[2]), "+f"(c[3])
        : "r"(a[0]), "r"(a[1]), "r"(b0));
}

extern __shared__ uint32_t smu[];

__global__ __launch_bounds__(THREADS, 1)
void softmesh_hmma7_kernel(
    const float* __restrict__ x, const float* __restrict__ y,
    const float* __restrict__ z,
    const float* __restrict__ W_in,  const float* __restrict__ b_in,
    const float* __restrict__ W_mid, const float* __restrict__ b_mid,
    const float* __restrict__ W_out, const float* __restrict__ b_out,
    float* __restrict__ out, int n)
{
    float* smf = (float*)smu;
    const int tid = threadIdx.x;

    // ---- Stage weight fragments hi+lo (once per persistent CTA) ----
    for (int i = tid; i < BF_SZ; i += THREADS) {
        int lane = (i & 63) >> 1, r = i & 1;
        int rest = i >> 6;
        int nb = rest % NB; rest /= NB;
        int kb = rest & 3;  int L = rest >> 2;
        int t = lane & 3, g = lane >> 2;
        int nn = nb * 8 + g;
        int k0 = kb * 16 + t * 2 + (r ? 8 : 0);
        float v0 = 0.f, v1 = 0.f;
        if (nn < HID) {
            if (L == 0) {
                if (k0 < 3)     v0 = W_in[k0 * HID + nn];
                if (k0 + 1 < 3) v1 = W_in[(k0 + 1) * HID + nn];
            } else {
                const float* W = W_mid + (size_t)(L - 1) * HID * HID;
                if (k0 < HID)     v0 = W[k0 * HID + nn];
                if (k0 + 1 < HID) v1 = W[(k0 + 1) * HID + nn];
            }
        }
        uint32_t hi, lo;
        split2(v0, v1, hi, lo);
        smu[BFH_OFF + i] = hi;
        smu[BFL_OFF + i] = lo;
    }
    for (int i = tid; i < OF_SZ; i += THREADS) {
        int lane = (i & 63) >> 1, r = i & 1;
        int kb = i >> 6;
        int t = lane & 3, g = lane >> 2;
        int nn = g;  // nblk 0 only
        int k0 = kb * 16 + t * 2 + (r ? 8 : 0);
        float v0 = 0.f, v1 = 0.f;
        if (nn < 3) {
            if (k0 < HID)     v0 = W_out[k0 * 3 + nn];
            if (k0 + 1 < HID) v1 = W_out[(k0 + 1) * 3 + nn];
        }
        uint32_t hi, lo;
        split2(v0, v1, hi, lo);
        smu[OFH_OFF + i] = hi;
        smu[OFL_OFF + i] = lo;
    }
    for (int i = tid; i < BIAS_SZ; i += THREADS) {
        int c = i & 1, t = (i >> 1) & 3;
        int rest = i >> 3;
        int nb = rest % NB, L = rest / NB;
        int col = nb * 8 + t * 2 + c;
        float v = 0.f;
        if (col < HID) v = (L == 0) ? b_in[col] : b_mid[(L - 1) * HID + col];
        smf[BIAS_OFF + i] = v;
    }
    if (tid < 8) {
        int c = tid & 1, t = tid >> 1;
        int col = t * 2 + c;
        smf[OBIAS_OFF + tid] = (col < 3) ? b_out[col] : 0.f;
    }
    __syncthreads();

    const int lane = tid & 31, w = tid >> 5;
    const int g = lane >> 2, t = lane & 3;
    const int ntiles = (n + TILE_M - 1) / TILE_M;

    for (int tile = blockIdx.x; tile < ntiles; tile += (int)gridDim.x) {
        const int p = tile * TILE_M + tid;

        // stage inputs (strictly intra-warp rows -> __syncwarp is enough)
        float xi = 0.f, yi = 0.f, zi = 0.f;
        if (p < n) { xi = x[p]; yi = y[p]; zi = z[p]; }
        smf[XYZ_OFF + tid]              = xi;
        smf[XYZ_OFF + TILE_M + tid]     = yi;
        smf[XYZ_OFF + 2 * TILE_M + tid] = zi;
        __syncwarp();

        uint32_t Ah[2][4][4], Al[2][4][4];
        float    c[2][NB][4];

        // ---- layer 0 A fragments (k<=3 -> only regs [0],[1] used, k8 MMA) ----
        #pragma unroll
        for (int m = 0; m < 2; ++m) {
            int r0 = w * 32 + m * 16 + g;
            int r1 = r0 + 8;
            uint32_t h0 = 0, h1 = 0, l0 = 0, l1 = 0;
            if (t == 0) {
                split2(smf[XYZ_OFF + r0], smf[XYZ_OFF + TILE_M + r0], h0, l0);
                split2(smf[XYZ_OFF + r1], smf[XYZ_OFF + TILE_M + r1], h1, l1);
            } else if (t == 1) {
                split2(smf[XYZ_OFF + 2 * TILE_M + r0], 0.f, h0, l0);
                split2(smf[XYZ_OFF + 2 * TILE_M + r1], 0.f, h1, l1);
            }
            Ah[m][0][0] = h0; Ah[m][0][1] = h1;
            Al[m][0][0] = l0; Al[m][0][1] = l1;
        }

        // ---- layer 0 GEMM: k8 MMAs (3 products), both m ----
        #pragma unroll
        for (int nb = 0; nb < NB; ++nb) {
            float2 bb = *(const float2*)&smf[BIAS_OFF + (nb * 4 + t) * 2];
            #pragma unroll
            for (int m = 0; m < 2; ++m) {
                c[m][nb][0] = bb.x; c[m][nb][1] = bb.y;
                c[m][nb][2] = bb.x; c[m][nb][3] = bb.y;
            }
            uint32_t bh = smu[BFH_OFF + nb * 64 + lane * 2];
            uint32_t bl = smu[BFL_OFF + nb * 64 + lane * 2];
            #pragma unroll
            for (int m = 0; m < 2; ++m) {
                mma16808(c[m][nb], Ah[m][0], bh);
                mma16808(c[m][nb], Ah[m][0], bl);
                mma16808(c[m][nb], Al[m][0], bh);
            }
        }

        // ---- layers 1..7, pipelined across the two m-tiles ----
        // per m: tanh (layer L-1 out) -> MMA (layer L). tanh(m1) is
        // independent of MMA(m0) and overlaps its tensor drain; tanh(m0) of
        // the next layer overlaps MMA(m1).
        #pragma unroll 1
        for (int L = 1; L < NLAYER; ++L) {
            const uint32_t* bhl = &smu[BFH_OFF + (size_t)L * 4 * NB * 64];
            const uint32_t* bll = &smu[BFL_OFF + (size_t)L * 4 * NB * 64];
            const float*    bil = &smf[BIAS_OFF + (size_t)L * NB * 8];
            #pragma unroll
            for (int m = 0; m < 2; ++m) {
                // tanh of previous-layer output for this m-tile
                #pragma unroll
                for (int kb = 0; kb < 3; ++kb) {
                    tanh_split2(c[m][2*kb][0],   c[m][2*kb][1],   Ah[m][kb][0], Al[m][kb][0]);
                    tanh_split2(c[m][2*kb][2],   c[m][2*kb][3],   Ah[m][kb][1], Al[m][kb][1]);
                    tanh_split2(c[m][2*kb+1][0], c[m][2*kb+1][1], Ah[m][kb][2], Al[m][kb][2]);
                    tanh_split2(c[m][2*kb+1][2], c[m][2*kb+1][3], Ah[m][kb][3], Al[m][kb][3]);
                }
                tanh_split2(c[m][6][0], c[m][6][1], Ah[m][3][0], Al[m][3][0]);
                tanh_split2(c[m][6][2], c[m][6][3], Ah[m][3][1], Al[m][3][1]);

                // bias re-init (after tanh consumed c) then MMAs for this m
                #pragma unroll
                for (int nb = 0; nb < NB; ++nb) {
                    float2 bb = *(const float2*)&bil[(nb * 4 + t) * 2];
                    c[m][nb][0] = bb.x; c[m][nb][1] = bb.y;
                    c[m][nb][2] = bb.x; c[m][nb][3] = bb.y;
                }
                #pragma unroll
                for (int kb = 0; kb < 3; ++kb) {
                    #pragma unroll
                    for (int nb = 0; nb < NB; ++nb) {
                        uint2 bh = *(const uint2*)&bhl[(kb * NB + nb) * 64 + lane * 2];
                        uint2 bl = *(const uint2*)&bll[(kb * NB + nb) * 64 + lane * 2];
                        mma16816(c[m][nb], Ah[m][kb], bh.x, bh.y);
                        mma16816(c[m][nb], Ah[m][kb], bl.x, bl.y);
                        mma16816(c[m][nb], Al[m][kb], bh.x, bh.y);
                    }
                }
                #pragma unroll
                for (int nb = 0; nb < NB; ++nb) {   // kb = 3: k8 (only k=48,49 real)
                    uint32_t bh = bhl[(3 * NB + nb) * 64 + lane * 2];
                    uint32_t bl = bll[(3 * NB + nb) * 64 + lane * 2];
                    mma16808(c[m][nb], Ah[m][3], bh);
                    mma16808(c[m][nb], Ah[m][3], bl);
                    mma16808(c[m][nb], Al[m][3], bh);
                }
            }
        }

        // ---- output layer 50->3 (nblk 0 only): tanh then out-MMA, per m ----
        float o[2][4];
        #pragma unroll
        for (int m = 0; m < 2; ++m) {
            #pragma unroll
            for (int kb = 0; kb < 3; ++kb) {
                tanh_split2(c[m][2*kb][0],   c[m][2*kb][1],   Ah[m][kb][0], Al[m][kb][0]);
                tanh_split2(c[m][2*kb][2],   c[m][2*kb][3],   Ah[m][kb][1], Al[m][kb][1]);
                tanh_split2(c[m][2*kb+1][0], c[m][2*kb+1][1], Ah[m][kb][2], Al[m][kb][2]);
                tanh_split2(c[m][2*kb+1][2], c[m][2*kb+1][3], Ah[m][kb][3], Al[m][kb][3]);
            }
            tanh_split2(c[m][6][0], c[m][6][1], Ah[m][3][0], Al[m][3][0]);
            tanh_split2(c[m][6][2], c[m][6][3], Ah[m][3][1], Al[m][3][1]);

            float2 bb = *(const float2*)&smf[OBIAS_OFF + t * 2];
            o[m][0] = bb.x; o[m][1] = bb.y; o[m][2] = bb.x; o[m][3] = bb.y;
            #pragma unroll
            for (int kb = 0; kb < 3; ++kb) {
                uint2 bh = *(const uint2*)&smu[OFH_OFF + kb * 64 + lane * 2];
                uint2 bl = *(const uint2*)&smu[OFL_OFF + kb * 64 + lane * 2];
                mma16816(o[m], Ah[m][kb], bh.x, bh.y);
                mma16816(o[m], Ah[m][kb], bl.x, bl.y);
                mma16816(o[m], Al[m][kb], bh.x, bh.y);
            }
            uint32_t bh = smu[OFH_OFF + 3 * 64 + lane * 2];
            uint32_t bl = smu[OFL_OFF + 3 * 64 + lane * 2];
            mma16808(o[m], Ah[m][3], bh);
            mma16808(o[m], Ah[m][3], bl);
            mma16808(o[m], Al[m][3], bh);
        }

        // scatter U to staging (intra-warp rows): t==0 -> cols 0,1 ; t==1 -> col 2
        #pragma unroll
        for (int m = 0; m < 2; ++m) {
            int r0 = w * 32 + m * 16 + g;
            int r1 = r0 + 8;
            if (t == 0) {
                smf[UOUT_OFF + r0] = o[m][0];
                smf[UOUT_OFF + TILE_M + r0] = o[m][1];
                smf[UOUT_OFF + r1] = o[m][2];
                smf[UOUT_OFF + TILE_M + r1] = o[m][3];
            } else if (t == 1) {
                smf[UOUT_OFF + 2 * TILE_M + r0] = o[m][0];
                smf[UOUT_OFF + 2 * TILE_M + r1] = o[m][2];
            }
        }
        __syncwarp();
        if (p < n) {
            out[p]         = smf[UOUT_OFF + tid];
            out[n + p]     = smf[UOUT_OFF + TILE_M + tid];
            out[2 * n + p] = smf[UOUT_OFF + 2 * TILE_M + tid];
        }
        __syncwarp();
    }
}

extern "C" void kernel_launch(void* const* d_in, const int* in_sizes, int n_in,
                              void* d_out, int out_size) {
    const float* x     = (const float*)d_in[0];
    const float* y     = (const float*)d_in[1];
    const float* z     = (const float*)d_in[2];
    const float* W_in  = (const float*)d_in[3];
    const float* b_in  = (const float*)d_in[4];
    const float* W_mid = (const float*)d_in[5];
    const float* b_mid = (const float*)d_in[6];
    const float* W_out = (const float*)d_in[7];
    const float* b_out = (const float*)d_in[8];
    float* out = (float*)d_out;
    const int n = in_sizes[0];

    const size_t smem_bytes = (size_t)SMEM_U32 * 4;
    cudaFuncSetAttribute(softmesh_hmma7_kernel,
                         cudaFuncAttributeMaxDynamicSharedMemorySize,
                         (int)smem_bytes);

    softmesh_hmma7_kernel<<<GRIDSZ, THREADS, smem_bytes>>>(
        x, y, z, W_in, b_in, W_mid, b_mid, W_out, b_out, out, n);
}

// round 16
// speedup vs baseline: 1.0953x; 1.0947x over previous
#include <cuda_runtime.h>
#include <cuda_fp16.h>
#include <cstdint>

// SoftMesh MLP via warp-level HMMA, SPLIT-FP16 operands (hi+lo), fp32 acc.
// [N,3] ->50 -> 7x(50 tanh) -> 3, N=2M.
// R15 = R11 base + kb3-elimination: k=48,49 contributions computed as EXACT
// fp32 FFMA (h48/h49 taken from fp32 accumulators pre-split, broadcast via
// shfl) instead of 3-product HMMA on a 2/16-utilized k-block. Cuts mid-layer
// MMA count 25% (168->126 per warp-tile-layer). kb tables shrink to 3 blocks.
// C += Ah*Bh + Ah*Bl + Al*Bh; ~22 effective mantissa bits (k48/49 exact).

#define HID 50
#define NB 7
#define NLAYER 8
#define TILE_M 384
#define THREADS 384
#define GRIDSZ 148

// SMEM layout (uint32 indices)
#define BFH_OFF  0
#define BF_SZ    (NLAYER * 3 * NB * 64)        // 10752 per set (kb 0..2 only)
#define BFL_OFF  (BFH_OFF + BF_SZ)
#define OFH_OFF  (BFL_OFF + BF_SZ)             // out-layer hi frags [kb<3][lane*2+r]
#define OF_SZ    (3 * 64)
#define OFL_OFF  (OFH_OFF + OF_SZ)
#define WT_OFF   (OFL_OFF + OF_SZ)             // float Wtail[7][56][2]: (W48,W49) per col
#define WT_SZ    (7 * 56 * 2)
#define OT_OFF   (WT_OFF + WT_SZ)              // float OTail[8][2]: (Wout48,Wout49) per col
#define OT_SZ    (8 * 2)
#define BIAS_OFF (OT_OFF + OT_SZ)              // float bias[L][nb][t][2]
#define BIAS_SZ  (NLAYER * NB * 4 * 2)
#define OBIAS_OFF (BIAS_OFF + BIAS_SZ)         // float [4][2]
#define OBIAS_SZ 8
#define XYZ_OFF  (OBIAS_OFF + OBIAS_SZ)        // float [3][TILE_M]
#define XYZ_SZ   (3 * TILE_M)
#define UOUT_OFF (XYZ_OFF + XYZ_SZ)            // float [3][TILE_M]
#define UOUT_SZ  (3 * TILE_M)
#define SMEM_U32 (UOUT_OFF + UOUT_SZ)

__device__ __forceinline__ uint32_t f16x2(float lo, float hi) {
    uint32_t r;
    asm("cvt.rn.f16x2.f32 %0, %1, %2;" : "=r"(r) : "f"(hi), "f"(lo));
    return r;
}
__device__ __forceinline__ void split2(float v0, float v1, uint32_t& hi, uint32_t& lo) {
    hi = f16x2(v0, v1);
    __half2 h2 = *reinterpret_cast<__half2*>(&hi);
    float2 b = __half22float2(h2);
    lo = f16x2(v0 - b.x, v1 - b.y);
}
// tanh on a pair with ONE shared rcp, fp32 results
__device__ __forceinline__ void tanh_pair(float x0, float x1, float& t0, float& t1) {
    const float K = 2.8853900817779268f;  // 2/ln2
    float e0, e1, r;
    asm("ex2.approx.f32 %0, %1;" : "=f"(e0) : "f"(x0 * K));
    asm("ex2.approx.f32 %0, %1;" : "=f"(e1) : "f"(x1 * K));
    float s0 = e0 + 1.0f, s1 = e1 + 1.0f;
    asm("rcp.approx.f32 %0, %1;" : "=f"(r) : "f"(s0 * s1));
    t0 = fmaf(-2.0f, s1 * r, 1.0f);
    t1 = fmaf(-2.0f, s0 * r, 1.0f);
}
__device__ __forceinline__ void tanh_split2(float x0, float x1, uint32_t& hi, uint32_t& lo) {
    float t0, t1;
    tanh_pair(x0, x1, t0, t1);
    split2(t0, t1, hi, lo);
}
__device__ __forceinline__ void mma16816(float* c, const uint32_t* a, uint32_t b0, uint32_t b1) {
    asm volatile(
        "mma.sync.aligned.m16n8k16.row.col.f32.f16.f16.f32 "
        "{%0,%1,%2,%3}, {%4,%5,%6,%7}, {%8,%9}, {%0,%1,%2,%3};"
        : "+f"(c[0]), "+f"(c[1]), "+f"(c[2]), "+f"(c[3])
        : "r"(a[0]), "r"(a[1]), "r"(a[2]), "r"(a[3]), "r"(b0), "r"(b1));
}
__device__ __forceinline__ void mma16808(float* c, const uint32_t* a, uint32_t b0) {
    asm volatile(
        "mma.sync.aligned.m16n8k8.row.col.f32.f16.f16.f32 "
        "{%0,%1,%2,%3}, {%4,%5}, {%6}, {%0,%1,%2,%3};"
        : "+f"(c[0]), "+f"(c[1]), "+f"(c[2]), "+f"(c[3])
        : "r"(a[0]), "r"(a[1]), "r"(b0));
}

extern __shared__ uint32_t smu[];

__global__ __launch_bounds__(THREADS, 1)
void softmesh_hmma8_kernel(
    const float* __restrict__ x, const float* __restrict__ y,
    const float* __restrict__ z,
    const float* __restrict__ W_in,  const float* __restrict__ b_in,
    const float* __restrict__ W_mid, const float* __restrict__ b_mid,
    const float* __restrict__ W_out, const float* __restrict__ b_out,
    float* __restrict__ out, int n)
{
    float* smf = (float*)smu;
    const int tid = threadIdx.x;

    // ---- Stage weight fragments hi+lo, kb 0..2 only (k < 48) ----
    for (int i = tid; i < BF_SZ; i += THREADS) {
        int lane = (i & 63) >> 1, r = i & 1;
        int rest = i >> 6;
        int nb = rest % NB; rest /= NB;
        int kb = rest % 3;  int L = rest / 3;
        int t = lane & 3, g = lane >> 2;
        int nn = nb * 8 + g;
        int k0 = kb * 16 + t * 2 + (r ? 8 : 0);
        float v0 = 0.f, v1 = 0.f;
        if (nn < HID) {
            if (L == 0) {
                if (k0 < 3)     v0 = W_in[k0 * HID + nn];
                if (k0 + 1 < 3) v1 = W_in[(k0 + 1) * HID + nn];
            } else {
                const float* W = W_mid + (size_t)(L - 1) * HID * HID;
                v0 = W[k0 * HID + nn];
                v1 = W[(k0 + 1) * HID + nn];
            }
        }
        uint32_t hi, lo;
        split2(v0, v1, hi, lo);
        smu[BFH_OFF + i] = hi;
        smu[BFL_OFF + i] = lo;
    }
    for (int i = tid; i < OF_SZ; i += THREADS) {
        int lane = (i & 63) >> 1, r = i & 1;
        int kb = i >> 6;
        int t = lane & 3, g = lane >> 2;
        int nn = g;  // nblk 0 only
        int k0 = kb * 16 + t * 2 + (r ? 8 : 0);
        float v0 = 0.f, v1 = 0.f;
        if (nn < 3) {
            v0 = W_out[k0 * 3 + nn];
            v1 = W_out[(k0 + 1) * 3 + nn];
        }
        uint32_t hi, lo;
        split2(v0, v1, hi, lo);
        smu[OFH_OFF + i] = hi;
        smu[OFL_OFF + i] = lo;
    }
    // fp32 weight tails: k = 48,49 rows of each mid layer / output layer
    for (int i = tid; i < WT_SZ; i += THREADS) {
        int which = i & 1;          // 0 -> W[48][col], 1 -> W[49][col]
        int col = (i >> 1) % 56;
        int Lm  = (i >> 1) / 56;    // 0..6 -> mid layer index
        float v = 0.f;
        if (col < HID) {
            const float* W = W_mid + (size_t)Lm * HID * HID;
            v = W[(48 + which) * HID + col];
        }
        smf[WT_OFF + i] = v;
    }
    if (tid < OT_SZ) {
        int which = tid & 1;
        int col = tid >> 1;        // 0..7
        smf[OT_OFF + tid] = (col < 3) ? W_out[(48 + which) * 3 + col] : 0.f;
    }
    for (int i = tid; i < BIAS_SZ; i += THREADS) {
        int c = i & 1, t = (i >> 1) & 3;
        int rest = i >> 3;
        int nb = rest % NB, L = rest / NB;
        int col = nb * 8 + t * 2 + c;
        float v = 0.f;
        if (col < HID) v = (L == 0) ? b_in[col] : b_mid[(L - 1) * HID + col];
        smf[BIAS_OFF + i] = v;
    }
    if (tid < 8) {
        int c = tid & 1, t = tid >> 1;
        int col = t * 2 + c;
        smf[OBIAS_OFF + tid] = (col < 3) ? b_out[col] : 0.f;
    }
    __syncthreads();

    const int lane = tid & 31, w = tid >> 5;
    const int g = lane >> 2, t = lane & 3;
    const int srcl = lane & ~3;          // t=0 lane of this group
    const int ntiles = (n + TILE_M - 1) / TILE_M;

    for (int tile = blockIdx.x; tile < ntiles; tile += (int)gridDim.x) {
        const int p = tile * TILE_M + tid;

        float xi = 0.f, yi = 0.f, zi = 0.f;
        if (p < n) { xi = x[p]; yi = y[p]; zi = z[p]; }
        smf[XYZ_OFF + tid]              = xi;
        smf[XYZ_OFF + TILE_M + tid]     = yi;
        smf[XYZ_OFF + 2 * TILE_M + tid] = zi;
        __syncwarp();

        uint32_t Ah[2][3][4], Al[2][3][4];
        float    c[2][NB][4];
        float    h48[2][2], h49[2][2];   // [m][row-half], fp32 exact tails

        // ---- layer 0 A fragments (k<=3 -> k8 MMA on kb0) ----
        #pragma unroll
        for (int m = 0; m < 2; ++m) {
            int r0 = w * 32 + m * 16 + g;
            int r1 = r0 + 8;
            uint32_t h0 = 0, h1 = 0, l0 = 0, l1 = 0;
            if (t == 0) {
                split2(smf[XYZ_OFF + r0], smf[XYZ_OFF + TILE_M + r0], h0, l0);
                split2(smf[XYZ_OFF + r1], smf[XYZ_OFF + TILE_M + r1], h1, l1);
            } else if (t == 1) {
                split2(smf[XYZ_OFF + 2 * TILE_M + r0], 0.f, h0, l0);
                split2(smf[XYZ_OFF + 2 * TILE_M + r1], 0.f, h1, l1);
            }
            Ah[m][0][0] = h0; Ah[m][0][1] = h1;
            Al[m][0][0] = l0; Al[m][0][1] = l1;
        }

        // ---- layer 0 GEMM: k8 MMAs (3 products), both m ----
        #pragma unroll
        for (int nb = 0; nb < NB; ++nb) {
            float2 bb = *(const float2*)&smf[BIAS_OFF + (nb * 4 + t) * 2];
            #pragma unroll
            for (int m = 0; m < 2; ++m) {
                c[m][nb][0] = bb.x; c[m][nb][1] = bb.y;
                c[m][nb][2] = bb.x; c[m][nb][3] = bb.y;
            }
            uint32_t bh = smu[BFH_OFF + nb * 64 + lane * 2];
            uint32_t bl = smu[BFL_OFF + nb * 64 + lane * 2];
            #pragma unroll
            for (int m = 0; m < 2; ++m) {
                mma16808(c[m][nb], Ah[m][0], bh);
                mma16808(c[m][nb], Ah[m][0], bl);
                mma16808(c[m][nb], Al[m][0], bh);
            }
        }
        // ---- tanh stage for layer-0 output ----
        #pragma unroll
        for (int m = 0; m < 2; ++m) {
            #pragma unroll
            for (int kb = 0; kb < 3; ++kb) {
                tanh_split2(c[m][2*kb][0],   c[m][2*kb][1],   Ah[m][kb][0], Al[m][kb][0]);
                tanh_split2(c[m][2*kb][2],   c[m][2*kb][3],   Ah[m][kb][1], Al[m][kb][1]);
                tanh_split2(c[m][2*kb+1][0], c[m][2*kb+1][1], Ah[m][kb][2], Al[m][kb][2]);
                tanh_split2(c[m][2*kb+1][2], c[m][2*kb+1][3], Ah[m][kb][3], Al[m][kb][3]);
            }
            float a0, a1, b0, b1;
            tanh_pair(c[m][6][0], c[m][6][1], a0, a1);   // row r0: h48, h49
            tanh_pair(c[m][6][2], c[m][6][3], b0, b1);   // row r1: h48, h49
            h48[m][0] = __shfl_sync(0xFFFFFFFFu, a0, srcl);
            h49[m][0] = __shfl_sync(0xFFFFFFFFu, a1, srcl);
            h48[m][1] = __shfl_sync(0xFFFFFFFFu, b0, srcl);
            h49[m][1] = __shfl_sync(0xFFFFFFFFu, b1, srcl);
        }

        // ---- layers 1..7: bias, MMA kb0..2, fp32 tail, tanh stage ----
        #pragma unroll 1
        for (int L = 1; L < NLAYER; ++L) {
            const uint32_t* bhl = &smu[BFH_OFF + (size_t)L * 3 * NB * 64];
            const uint32_t* bll = &smu[BFL_OFF + (size_t)L * 3 * NB * 64];
            const float*    bil = &smf[BIAS_OFF + (size_t)L * NB * 8];
            const float*    wtl = &smf[WT_OFF + (size_t)(L - 1) * 112];
            #pragma unroll
            for (int nb = 0; nb < NB; ++nb) {
                float2 bb = *(const float2*)&bil[(nb * 4 + t) * 2];
                #pragma unroll
                for (int m = 0; m < 2; ++m) {
                    c[m][nb][0] = bb.x; c[m][nb][1] = bb.y;
                    c[m][nb][2] = bb.x; c[m][nb][3] = bb.y;
                }
            }
            #pragma unroll
            for (int kb = 0; kb < 3; ++kb) {
                #pragma unroll
                for (int nb = 0; nb < NB; ++nb) {
                    uint2 bh = *(const uint2*)&bhl[(kb * NB + nb) * 64 + lane * 2];
                    uint2 bl = *(const uint2*)&bll[(kb * NB + nb) * 64 + lane * 2];
                    #pragma unroll
                    for (int m = 0; m < 2; ++m) {
                        mma16816(c[m][nb], Ah[m][kb], bh.x, bh.y);
                        mma16816(c[m][nb], Ah[m][kb], bl.x, bl.y);
                        mma16816(c[m][nb], Al[m][kb], bh.x, bh.y);
                    }
                }
            }
            // exact fp32 tail: k = 48, 49
            #pragma unroll
            for (int nb = 0; nb < NB; ++nb) {
                float2 w0 = *(const float2*)&wtl[(nb * 8 + t * 2) * 2];
                float2 w1 = *(const float2*)&wtl[(nb * 8 + t * 2 + 1) * 2];
                #pragma unroll
                for (int m = 0; m < 2; ++m) {
                    c[m][nb][0] = fmaf(h49[m][0], w0.y, fmaf(h48[m][0], w0.x, c[m][nb][0]));
                    c[m][nb][1] = fmaf(h49[m][0], w1.y, fmaf(h48[m][0], w1.x, c[m][nb][1]));
                    c[m][nb][2] = fmaf(h49[m][1], w0.y, fmaf(h48[m][1], w0.x, c[m][nb][2]));
                    c[m][nb][3] = fmaf(h49[m][1], w1.y, fmaf(h48[m][1], w1.x, c[m][nb][3]));
                }
            }
            // tanh stage -> next layer's A fragments + fp32 tails
            #pragma unroll
            for (int m = 0; m < 2; ++m) {
                #pragma unroll
                for (int kb = 0; kb < 3; ++kb) {
                    tanh_split2(c[m][2*kb][0],   c[m][2*kb][1],   Ah[m][kb][0], Al[m][kb][0]);
                    tanh_split2(c[m][2*kb][2],   c[m][2*kb][3],   Ah[m][kb][1], Al[m][kb][1]);
                    tanh_split2(c[m][2*kb+1][0], c[m][2*kb+1][1], Ah[m][kb][2], Al[m][kb][2]);
                    tanh_split2(c[m][2*kb+1][2], c[m][2*kb+1][3], Ah[m][kb][3], Al[m][kb][3]);
                }
                float a0, a1, b0, b1;
                tanh_pair(c[m][6][0], c[m][6][1], a0, a1);
                tanh_pair(c[m][6][2], c[m][6][3], b0, b1);
                h48[m][0] = __shfl_sync(0xFFFFFFFFu, a0, srcl);
                h49[m][0] = __shfl_sync(0xFFFFFFFFu, a1, srcl);
                h48[m][1] = __shfl_sync(0xFFFFFFFFu, b0, srcl);
                h49[m][1] = __shfl_sync(0xFFFFFFFFu, b1, srcl);
            }
        }

        // ---- output layer 50->3 (nblk 0 only) ----
        float o[2][4];
        {
            float2 bb = *(const float2*)&smf[OBIAS_OFF + t * 2];
            #pragma unroll
            for (int m = 0; m < 2; ++m) {
                o[m][0] = bb.x; o[m][1] = bb.y; o[m][2] = bb.x; o[m][3] = bb.y;
            }
            #pragma unroll
            for (int kb = 0; kb < 3; ++kb) {
                uint2 bh = *(const uint2*)&smu[OFH_OFF + kb * 64 + lane * 2];
                uint2 bl = *(const uint2*)&smu[OFL_OFF + kb * 64 + lane * 2];
                #pragma unroll
                for (int m = 0; m < 2; ++m) {
                    mma16816(o[m], Ah[m][kb], bh.x, bh.y);
                    mma16816(o[m], Ah[m][kb], bl.x, bl.y);
                    mma16816(o[m], Al[m][kb], bh.x, bh.y);
                }
            }
            float2 w0 = *(const float2*)&smf[OT_OFF + (t * 2) * 2];
            float2 w1 = *(const float2*)&smf[OT_OFF + (t * 2 + 1) * 2];
            #pragma unroll
            for (int m = 0; m < 2; ++m) {
                o[m][0] = fmaf(h49[m][0], w0.y, fmaf(h48[m][0], w0.x, o[m][0]));
                o[m][1] = fmaf(h49[m][0], w1.y, fmaf(h48[m][0], w1.x, o[m][1]));
                o[m][2] = fmaf(h49[m][1], w0.y, fmaf(h48[m][1], w0.x, o[m][2]));
                o[m][3] = fmaf(h49[m][1], w1.y, fmaf(h48[m][1], w1.x, o[m][3]));
            }
        }
        // scatter U to staging (intra-warp rows): t==0 -> cols 0,1 ; t==1 -> col 2
        #pragma unroll
        for (int m = 0; m < 2; ++m) {
            int r0 = w * 32 + m * 16 + g;
            int r1 = r0 + 8;
            if (t == 0) {
                smf[UOUT_OFF + r0] = o[m][0];
                smf[UOUT_OFF + TILE_M + r0] = o[m][1];
                smf[UOUT_OFF + r1] = o[m][2];
                smf[UOUT_OFF + TILE_M + r1] = o[m][3];
            } else if (t == 1) {
                smf[UOUT_OFF + 2 * TILE_M + r0] = o[m][0];
                smf[UOUT_OFF + 2 * TILE_M + r1] = o[m][2];
            }
        }
        __syncwarp();
        if (p < n) {
            out[p]         = smf[UOUT_OFF + tid];
            out[n + p]     = smf[UOUT_OFF + TILE_M + tid];
            out[2 * n + p] = smf[UOUT_OFF + 2 * TILE_M + tid];
        }
        __syncwarp();
    }
}

extern "C" void kernel_launch(void* const* d_in, const int* in_sizes, int n_in,
                              void* d_out, int out_size) {
    const float* x     = (const float*)d_in[0];
    const float* y     = (const float*)d_in[1];
    const float* z     = (const float*)d_in[2];
    const float* W_in  = (const float*)d_in[3];
    const float* b_in  = (const float*)d_in[4];
    const float* W_mid = (const float*)d_in[5];
    const float* b_mid = (const float*)d_in[6];
    const float* W_out = (const float*)d_in[7];
    const float* b_out = (const float*)d_in[8];
    float* out = (float*)d_out;
    const int n = in_sizes[0];

    const size_t smem_bytes = (size_t)SMEM_U32 * 4;
    cudaFuncSetAttribute(softmesh_hmma8_kernel,
                         cudaFuncAttributeMaxDynamicSharedMemorySize,
                         (int)smem_bytes);

    softmesh_hmma8_kernel<<<GRIDSZ, THREADS, smem_bytes>>>(
        x, y, z, W_in, b_in, W_mid, b_mid, W_out, b_out, out, n);
}